// round 4
// baseline (speedup 1.0000x reference)
#include <cuda_runtime.h>
#include <cuda_fp16.h>
#include <cstdint>

// Problem constants
#define BB 8
#define TT 256
#define MM 64
#define DD 512
#define HH 8
#define DKK 64
#define NROWS (BB*TT*MM)        // 131072
#define NBTH  (BB*TT*HH)        // 16384

// Scratch (device globals: allocation-free)
__device__ __half g_xh[(size_t)NROWS*DD];      // X in fp16
__device__ __half g_wqkv[3*DD*DD];             // packed Wq|Wk|Wv fp16 (rows = features)
__device__ __half g_wo[DD*DD];                 // Wo fp16
__device__ __half g_q[(size_t)NBTH*MM*DKK];    // (bt,h,m,dk) fp16
__device__ __half g_k[(size_t)NBTH*MM*DKK];
__device__ __half g_v[(size_t)NBTH*MM*DKK];
__device__ __half g_a[(size_t)NROWS*DD];       // (btm, d) fp16 attention output

__device__ __forceinline__ uint32_t smem_u32(const void* p) {
    uint32_t a;
    asm("{ .reg .u64 t; cvta.to.shared.u64 t, %1; cvt.u32.u64 %0, t; }" : "=r"(a) : "l"(p));
    return a;
}
__device__ __forceinline__ void cp16(uint32_t saddr, const void* gaddr) {
    asm volatile("cp.async.cg.shared.global [%0], [%1], 16;" :: "r"(saddr), "l"(gaddr) : "memory");
}
__device__ __forceinline__ void cp_commit() {
    asm volatile("cp.async.commit_group;" ::: "memory");
}
__device__ __forceinline__ void ldsm4(uint32_t& r0, uint32_t& r1, uint32_t& r2, uint32_t& r3,
                                      uint32_t addr) {
    asm volatile("ldmatrix.sync.aligned.m8n8.x4.shared.b16 {%0,%1,%2,%3}, [%4];"
        : "=r"(r0), "=r"(r1), "=r"(r2), "=r"(r3) : "r"(addr));
}

__device__ __forceinline__ void mma_f16(float* c,
    uint32_t a0, uint32_t a1, uint32_t a2, uint32_t a3, uint32_t b0, uint32_t b1)
{
    asm volatile(
        "mma.sync.aligned.m16n8k16.row.col.f32.f16.f16.f32 "
        "{%0,%1,%2,%3}, {%4,%5,%6,%7}, {%8,%9}, {%0,%1,%2,%3};"
        : "+f"(c[0]), "+f"(c[1]), "+f"(c[2]), "+f"(c[3])
        : "r"(a0), "r"(a1), "r"(a2), "r"(a3), "r"(b0), "r"(b1));
}

// ---------------------------------------------------------------------------
// conv kernels: fp32 -> fp16
// ---------------------------------------------------------------------------
__global__ void conv_h(const float4* __restrict__ in, uint2* __restrict__ out, int n4)
{
    int i = blockIdx.x * blockDim.x + threadIdx.x;
    if (i >= n4) return;
    float4 v = in[i];
    __half2 h0 = __floats2half2_rn(v.x, v.y);
    __half2 h1 = __floats2half2_rn(v.z, v.w);
    uint2 r;
    r.x = *(uint32_t*)&h0;
    r.y = *(uint32_t*)&h1;
    out[i] = r;
}

// all 4 weight matrices in one launch (each DD*DD/4 = 65536 float4s)
__global__ void conv_w(const float4* __restrict__ wq, const float4* __restrict__ wk,
                       const float4* __restrict__ wv, const float4* __restrict__ wo,
                       uint2* __restrict__ oqkv, uint2* __restrict__ oo)
{
    int i = blockIdx.x * blockDim.x + threadIdx.x;   // 0 .. 4*65536-1
    int t = i >> 16, j = i & 65535;
    const float4* src = (t == 0) ? wq : (t == 1) ? wk : (t == 2) ? wv : wo;
    uint2* dst = (t == 3) ? oo : (oqkv + (size_t)t * (DD*DD/4));
    float4 v = src[j];
    __half2 h0 = __floats2half2_rn(v.x, v.y);
    __half2 h1 = __floats2half2_rn(v.z, v.w);
    uint2 r;
    r.x = *(uint32_t*)&h0;
    r.y = *(uint32_t*)&h1;
    dst[j] = r;
}

// ---------------------------------------------------------------------------
// fp16 GEMM: D[128 x 128] block of Y = A(rows,512) @ B(cols,512)^T + bias
// 3-stage cp.async pipeline, BK=64, XOR-swizzled 128B smem rows, ldmatrix.x4.
// 8 warps (4x2), warp tile 32x64.
// MODE 0 (QKV fused, N=1536): store fp16 via smem to (bt,h,m,dk) in q/k/v.
// MODE 1 (out-proj): store fp32 direct to out[r*512+col].
// ---------------------------------------------------------------------------
#define STG 32768                 // per-stage bytes: A 16KB + B 16KB
#define GEMM_SMEM (3*STG)

__device__ __forceinline__ void fill_stage(uint32_t smem_base, int s,
                                           const __half* __restrict__ Ap,
                                           const __half* __restrict__ Bp,
                                           int kt, int tid)
{
    uint32_t As = smem_base + s * STG;
    uint32_t Bs = As + 16384;
    int koff = kt * 64;
    #pragma unroll
    for (int it = 0; it < 4; it++) {
        int i = tid + it * 256;
        int r = i >> 3, c8 = i & 7;
        cp16(As + r * 128 + ((c8 ^ (r & 7)) << 4), Ap + (size_t)r * 512 + koff + c8 * 8);
    }
    #pragma unroll
    for (int it = 0; it < 4; it++) {
        int i = tid + it * 256;
        int r = i >> 3, c8 = i & 7;
        cp16(Bs + r * 128 + ((c8 ^ (r & 7)) << 4), Bp + (size_t)r * 512 + koff + c8 * 8);
    }
    cp_commit();
}

template<int MODE>
__global__ __launch_bounds__(256, 2)
void gemm_f16(const __half* __restrict__ A, const __half* __restrict__ Bw,
              const float* __restrict__ bq, const float* __restrict__ bk,
              const float* __restrict__ bv,
              void* __restrict__ dq, void* __restrict__ dk_, void* __restrict__ dv)
{
    extern __shared__ char sm[];
    const int tid = threadIdx.x, wid = tid >> 5, lane = tid & 31;
    const int g = lane >> 2, tg = lane & 3;
    const int n0 = blockIdx.x * 128, m0 = blockIdx.y * 128;
    const int wm = (wid & 3) * 32, wn = (wid >> 2) * 64;

    // ldmatrix addressing: row = base + (lane&15), k-chunk += (lane>>4)
    const int lr = lane & 15, ls = lane >> 4;
    const int sxor = lane & 7;          // (row & 7) for all our rows (bases are %32==0 or +16)

    uint32_t sbase = smem_u32(sm);
    const __half* Ap = A + (size_t)m0 * 512;
    const __half* Bp = Bw + (size_t)n0 * 512;

    float acc[2][8][4];
    #pragma unroll
    for (int a = 0; a < 2; a++)
        #pragma unroll
        for (int b = 0; b < 8; b++)
            #pragma unroll
            for (int c = 0; c < 4; c++) acc[a][b][c] = 0.f;

    fill_stage(sbase, 0, Ap, Bp, 0, tid);
    fill_stage(sbase, 1, Ap, Bp, 1, tid);

    for (int kt = 0; kt < 8; kt++) {
        if (kt < 7) asm volatile("cp.async.wait_group 1;" ::: "memory");
        else        asm volatile("cp.async.wait_group 0;" ::: "memory");
        __syncthreads();
        if (kt + 2 < 8) fill_stage(sbase, (kt + 2) % 3, Ap, Bp, kt + 2, tid);

        uint32_t As = sbase + (kt % 3) * STG;
        uint32_t Bs = As + 16384;
        uint32_t a_base0 = As + (wm + lr) * 128;
        uint32_t a_base1 = a_base0 + 16 * 128;
        uint32_t b_base0 = Bs + (wn + lr) * 128;

        #pragma unroll
        for (int ks = 0; ks < 4; ks++) {
            uint32_t sel = (uint32_t)(((2 * ks + ls) ^ sxor) << 4);
            uint32_t af[2][4], bf[8][2];
            ldsm4(af[0][0], af[0][1], af[0][2], af[0][3], a_base0 + sel);
            ldsm4(af[1][0], af[1][1], af[1][2], af[1][3], a_base1 + sel);
            #pragma unroll
            for (int b = 0; b < 4; b++) {
                uint32_t r0, r1, r2, r3;
                ldsm4(r0, r1, r2, r3, b_base0 + b * 16 * 128 + sel);
                bf[2*b  ][0] = r0; bf[2*b+1][0] = r1;
                bf[2*b  ][1] = r2; bf[2*b+1][1] = r3;
            }
            #pragma unroll
            for (int im = 0; im < 2; im++)
                #pragma unroll
                for (int in = 0; in < 8; in++)
                    mma_f16(acc[im][in], af[im][0], af[im][1], af[im][2], af[im][3],
                            bf[in][0], bf[in][1]);
        }
    }

    if (MODE == 0) {
        __syncthreads();   // all warps done reading stage smem before C-tile reuse
        // pick tensor + bias by n-block
        int t = n0 >> 9, nc0 = n0 & 511, h0 = nc0 >> 6;
        const float* bias = (t == 0 ? bq : t == 1 ? bk : bv) + nc0;
        __half* dst_t = (__half*)(t == 0 ? dq : t == 1 ? dk_ : dv);

        // acc (+bias) -> smem fp16 tile Cs[128][136]
        #pragma unroll
        for (int im = 0; im < 2; im++) {
            #pragma unroll
            for (int in = 0; in < 8; in++) {
                int col = wn + in * 8 + 2 * tg;
                float bb0 = bias[col], bb1 = bias[col + 1];
                int r0 = wm + im * 16 + g;
                *(__half2*)(sm + r0 * 272 + col * 2) =
                    __floats2half2_rn(acc[im][in][0] + bb0, acc[im][in][1] + bb1);
                *(__half2*)(sm + (r0 + 8) * 272 + col * 2) =
                    __floats2half2_rn(acc[im][in][2] + bb0, acc[im][in][3] + bb1);
            }
        }
        __syncthreads();

        // coalesced stores: thread = (m, h-block); 64 contiguous halves each
        int m = tid >> 1, hb = tid & 1;
        int r = m0 + m, bt = r >> 6, mm = r & 63;
        __half* dst = dst_t + (((size_t)(bt * 8 + h0 + hb) * 64 + mm) * 64);
        const uint4* srcp = (const uint4*)(sm + m * 272 + hb * 128);
        uint4* dstp = (uint4*)dst;
        #pragma unroll
        for (int j = 0; j < 8; j++) dstp[j] = srcp[j];
    } else {
        // direct fp32 stores
        float* out = (float*)dq;
        const float* bias = bq;
        #pragma unroll
        for (int im = 0; im < 2; im++) {
            #pragma unroll
            for (int in = 0; in < 8; in++) {
                int col = n0 + wn + in * 8 + 2 * tg;
                float bb0 = bias[col], bb1 = bias[col + 1];
                int r0 = m0 + wm + im * 16 + g;
                float2 v0 = {acc[im][in][0] + bb0, acc[im][in][1] + bb1};
                float2 v1 = {acc[im][in][2] + bb0, acc[im][in][3] + bb1};
                *(float2*)(out + (size_t)r0 * 512 + col) = v0;
                *(float2*)(out + (size_t)(r0 + 8) * 512 + col) = v1;
            }
        }
    }
}

// ---------------------------------------------------------------------------
// Attention (fp16): one CTA per (bt, h). q,k,v tiles (bt,h,m,dk) fp16.
// scores = q@k^T/8 -> softmax -> p@v. Writes g_a[(btm, d)] fp16.
// ---------------------------------------------------------------------------
__global__ __launch_bounds__(128)
void attn_kernel()
{
    __shared__ __half qs[64 * 72];
    __shared__ __half ks_[64 * 72];
    __shared__ __half vs[64 * 72];   // [dk][m'] (transposed)
    __shared__ __half ss[64 * 72];   // P [m][m']

    const int bth = blockIdx.x;
    const int bt = bth >> 3, h = bth & 7;
    const __half* qg = g_q + (size_t)bth * 4096;
    const __half* kg = g_k + (size_t)bth * 4096;
    const __half* vg = g_v + (size_t)bth * 4096;

    const int tid = threadIdx.x;

    // stage q,k (direct [m][dk]) and v (transpose -> [dk][m'])
    #pragma unroll
    for (int it = 0; it < 4; it++) {
        int i = tid + it * 128;
        int r = i >> 3, c8 = i & 7;
        *(uint4*)(qs + r * 72 + c8 * 8) = *(const uint4*)(qg + r * 64 + c8 * 8);
        *(uint4*)(ks_ + r * 72 + c8 * 8) = *(const uint4*)(kg + r * 64 + c8 * 8);
        uint4 vv = *(const uint4*)(vg + r * 64 + c8 * 8);
        const __half* hv = (const __half*)&vv;
        #pragma unroll
        for (int j = 0; j < 8; j++) vs[(c8 * 8 + j) * 72 + r] = hv[j];
    }
    __syncthreads();

    const int w = tid >> 5, lane = tid & 31;
    const int g = lane >> 2, tg = lane & 3;
    const int mr = w * 16;

    float c[8][4];
    #pragma unroll
    for (int in = 0; in < 8; in++)
        #pragma unroll
        for (int j = 0; j < 4; j++) c[in][j] = 0.f;

    // scores = q @ k^T  (A = qs[m][dk], B = ks[m'][dk], k-major both)
    #pragma unroll
    for (int ks4 = 0; ks4 < 4; ks4++) {
        int koff = ks4 * 16;
        uint32_t a0 = *(uint32_t*)(qs + (mr + g    ) * 72 + koff + 2 * tg);
        uint32_t a1 = *(uint32_t*)(qs + (mr + g + 8) * 72 + koff + 2 * tg);
        uint32_t a2 = *(uint32_t*)(qs + (mr + g    ) * 72 + koff + 2 * tg + 8);
        uint32_t a3 = *(uint32_t*)(qs + (mr + g + 8) * 72 + koff + 2 * tg + 8);
        #pragma unroll
        for (int in = 0; in < 8; in++) {
            int nr = in * 8 + g;
            uint32_t b0 = *(uint32_t*)(ks_ + nr * 72 + koff + 2 * tg);
            uint32_t b1 = *(uint32_t*)(ks_ + nr * 72 + koff + 2 * tg + 8);
            mma_f16(c[in], a0, a1, a2, a3, b0, b1);
        }
    }

    const float scale = 0.125f;
    float mx0 = -1e30f, mx1 = -1e30f;
    #pragma unroll
    for (int in = 0; in < 8; in++) {
        c[in][0] *= scale; c[in][1] *= scale;
        c[in][2] *= scale; c[in][3] *= scale;
        mx0 = fmaxf(mx0, fmaxf(c[in][0], c[in][1]));
        mx1 = fmaxf(mx1, fmaxf(c[in][2], c[in][3]));
    }
    mx0 = fmaxf(mx0, __shfl_xor_sync(0xffffffffu, mx0, 1));
    mx0 = fmaxf(mx0, __shfl_xor_sync(0xffffffffu, mx0, 2));
    mx1 = fmaxf(mx1, __shfl_xor_sync(0xffffffffu, mx1, 1));
    mx1 = fmaxf(mx1, __shfl_xor_sync(0xffffffffu, mx1, 2));

    float s0 = 0.f, s1 = 0.f;
    #pragma unroll
    for (int in = 0; in < 8; in++) {
        c[in][0] = __expf(c[in][0] - mx0); s0 += c[in][0];
        c[in][1] = __expf(c[in][1] - mx0); s0 += c[in][1];
        c[in][2] = __expf(c[in][2] - mx1); s1 += c[in][2];
        c[in][3] = __expf(c[in][3] - mx1); s1 += c[in][3];
    }
    s0 += __shfl_xor_sync(0xffffffffu, s0, 1);
    s0 += __shfl_xor_sync(0xffffffffu, s0, 2);
    s1 += __shfl_xor_sync(0xffffffffu, s1, 1);
    s1 += __shfl_xor_sync(0xffffffffu, s1, 2);
    float inv0 = 1.f / s0, inv1 = 1.f / s1;

    #pragma unroll
    for (int in = 0; in < 8; in++) {
        int col = in * 8 + 2 * tg;
        *(__half2*)(ss + (mr + g    ) * 72 + col) = __floats2half2_rn(c[in][0] * inv0, c[in][1] * inv0);
        *(__half2*)(ss + (mr + g + 8) * 72 + col) = __floats2half2_rn(c[in][2] * inv1, c[in][3] * inv1);
    }
    __syncwarp();

    #pragma unroll
    for (int in = 0; in < 8; in++)
        #pragma unroll
        for (int j = 0; j < 4; j++) c[in][j] = 0.f;

    // out = P @ V  (A = ss[m][m'], B[k=m'][n=dk] = vs[dk][m'])
    #pragma unroll
    for (int ks4 = 0; ks4 < 4; ks4++) {
        int koff = ks4 * 16;
        uint32_t a0 = *(uint32_t*)(ss + (mr + g    ) * 72 + koff + 2 * tg);
        uint32_t a1 = *(uint32_t*)(ss + (mr + g + 8) * 72 + koff + 2 * tg);
        uint32_t a2 = *(uint32_t*)(ss + (mr + g    ) * 72 + koff + 2 * tg + 8);
        uint32_t a3 = *(uint32_t*)(ss + (mr + g + 8) * 72 + koff + 2 * tg + 8);
        #pragma unroll
        for (int in = 0; in < 8; in++) {
            int nr = in * 8 + g;
            uint32_t b0 = *(uint32_t*)(vs + nr * 72 + koff + 2 * tg);
            uint32_t b1 = *(uint32_t*)(vs + nr * 72 + koff + 2 * tg + 8);
            mma_f16(c[in], a0, a1, a2, a3, b0, b1);
        }
    }

    // store fp16 to g_a[(bt*64+m)*512 + h*64 + col]
    __half* dst = g_a + ((size_t)bt * 64) * 512 + h * 64;
    #pragma unroll
    for (int in = 0; in < 8; in++) {
        int col = in * 8 + 2 * tg;
        *(__half2*)(dst + (size_t)(mr + g    ) * 512 + col) = __floats2half2_rn(c[in][0], c[in][1]);
        *(__half2*)(dst + (size_t)(mr + g + 8) * 512 + col) = __floats2half2_rn(c[in][2], c[in][3]);
    }
}

// ---------------------------------------------------------------------------
extern "C" void kernel_launch(void* const* d_in, const int* in_sizes, int n_in,
                              void* d_out, int out_size)
{
    const float* x  = (const float*)d_in[0];
    const float* Wq = (const float*)d_in[1];
    const float* bq = (const float*)d_in[2];
    const float* Wk = (const float*)d_in[3];
    const float* bk = (const float*)d_in[4];
    const float* Wv = (const float*)d_in[5];
    const float* bv = (const float*)d_in[6];
    const float* Wo = (const float*)d_in[7];
    const float* bo = (const float*)d_in[8];
    float* out = (float*)d_out;

    void *pxh, *pwqkv, *pwo, *pq, *pk, *pv, *pa;
    cudaGetSymbolAddress(&pxh,   g_xh);
    cudaGetSymbolAddress(&pwqkv, g_wqkv);
    cudaGetSymbolAddress(&pwo,   g_wo);
    cudaGetSymbolAddress(&pq,    g_q);
    cudaGetSymbolAddress(&pk,    g_k);
    cudaGetSymbolAddress(&pv,    g_v);
    cudaGetSymbolAddress(&pa,    g_a);
    __half* wqkv = (__half*)pwqkv;

    // 1) fp32 -> fp16 conversions (x + all 4 weights in 2 launches)
    conv_h<<<(NROWS*DD/4 + 255)/256, 256>>>((const float4*)x, (uint2*)pxh, NROWS*DD/4);
    conv_w<<<(4*DD*DD/4 + 255)/256, 256>>>((const float4*)Wq, (const float4*)Wk,
                                           (const float4*)Wv, (const float4*)Wo,
                                           (uint2*)pwqkv, (uint2*)pwo);

    cudaFuncSetAttribute(gemm_f16<0>, cudaFuncAttributeMaxDynamicSharedMemorySize, GEMM_SMEM);
    cudaFuncSetAttribute(gemm_f16<1>, cudaFuncAttributeMaxDynamicSharedMemorySize, GEMM_SMEM);

    // 2) fused QKV projection: N = 1536
    dim3 gqkv(12, NROWS / 128);
    gemm_f16<0><<<gqkv, 256, GEMM_SMEM>>>((const __half*)pxh, wqkv,
                                          bq, bk, bv, pq, pk, pv);

    // 3) attention
    attn_kernel<<<NBTH, 128>>>();

    // 4) output projection: N = 512, fp32 out
    dim3 go(4, NROWS / 128);
    gemm_f16<1><<<go, 256, GEMM_SMEM>>>((const __half*)pa, (const __half*)pwo,
                                        bo, nullptr, nullptr, out, nullptr, nullptr);
}

// round 5
// speedup vs baseline: 1.4565x; 1.4565x over previous
#include <cuda_runtime.h>
#include <cuda_fp16.h>
#include <cstdint>

// Problem constants
#define BB 8
#define TT 256
#define MM 64
#define DD 512
#define HH 8
#define DKK 64
#define NROWS (BB*TT*MM)        // 131072
#define NBTH  (BB*TT*HH)        // 16384

// Scratch (device globals: allocation-free)
__device__ __half g_xh[(size_t)NROWS*DD];      // X in fp16
__device__ __half g_wqkv[3*DD*DD];             // packed Wq|Wk|Wv fp16 (rows = features)
__device__ __half g_wo[DD*DD];                 // Wo fp16
__device__ __half g_q[(size_t)NBTH*MM*DKK];    // (bt,h,m,dk) fp16
__device__ __half g_k[(size_t)NBTH*MM*DKK];
__device__ __half g_v[(size_t)NBTH*MM*DKK];
__device__ __half g_a[(size_t)NROWS*DD];       // (btm, d) fp16 attention output

__device__ __forceinline__ uint32_t smem_u32(const void* p) {
    uint32_t a;
    asm("{ .reg .u64 t; cvta.to.shared.u64 t, %1; cvt.u32.u64 %0, t; }" : "=r"(a) : "l"(p));
    return a;
}
__device__ __forceinline__ void cp16(uint32_t saddr, const void* gaddr) {
    asm volatile("cp.async.cg.shared.global [%0], [%1], 16;" :: "r"(saddr), "l"(gaddr) : "memory");
}
__device__ __forceinline__ void cp_commit() {
    asm volatile("cp.async.commit_group;" ::: "memory");
}

__device__ __forceinline__ void mma_f16(float* c,
    uint32_t a0, uint32_t a1, uint32_t a2, uint32_t a3, uint32_t b0, uint32_t b1)
{
    asm volatile(
        "mma.sync.aligned.m16n8k16.row.col.f32.f16.f16.f32 "
        "{%0,%1,%2,%3}, {%4,%5,%6,%7}, {%8,%9}, {%0,%1,%2,%3};"
        : "+f"(c[0]), "+f"(c[1]), "+f"(c[2]), "+f"(c[3])
        : "r"(a0), "r"(a1), "r"(a2), "r"(a3), "r"(b0), "r"(b1));
}

// ---------------------------------------------------------------------------
// conv kernels: fp32 -> fp16
// ---------------------------------------------------------------------------
__global__ void conv_h(const float4* __restrict__ in, uint2* __restrict__ out, int n4)
{
    int i = blockIdx.x * blockDim.x + threadIdx.x;
    if (i >= n4) return;
    float4 v = in[i];
    __half2 h0 = __floats2half2_rn(v.x, v.y);
    __half2 h1 = __floats2half2_rn(v.z, v.w);
    uint2 r;
    r.x = *(uint32_t*)&h0;
    r.y = *(uint32_t*)&h1;
    out[i] = r;
}

__global__ void conv_w(const float4* __restrict__ wq, const float4* __restrict__ wk,
                       const float4* __restrict__ wv, const float4* __restrict__ wo,
                       uint2* __restrict__ oqkv, uint2* __restrict__ oo)
{
    int i = blockIdx.x * blockDim.x + threadIdx.x;   // 0 .. 4*65536-1
    int t = i >> 16, j = i & 65535;
    const float4* src = (t == 0) ? wq : (t == 1) ? wk : (t == 2) ? wv : wo;
    uint2* dst = (t == 3) ? oo : (oqkv + (size_t)t * (DD*DD/4));
    float4 v = src[j];
    __half2 h0 = __floats2half2_rn(v.x, v.y);
    __half2 h1 = __floats2half2_rn(v.z, v.w);
    uint2 r;
    r.x = *(uint32_t*)&h0;
    r.y = *(uint32_t*)&h1;
    dst[j] = r;
}

// ---------------------------------------------------------------------------
// fp16 GEMM (R3-proven): D[128 x 128] block of Y = A(rows,512) @ B(cols,512)^T
// 3-stage cp.async pipeline, BK=64, XOR-swizzled 128B smem rows, scalar LDS.
// ---------------------------------------------------------------------------
#define STG 32768                 // per-stage bytes: A 16KB + B 16KB
#define GEMM_SMEM (3*STG)

__device__ __forceinline__ void fill_stage(uint32_t smem_base, int s,
                                           const __half* __restrict__ Ap,
                                           const __half* __restrict__ Bp,
                                           int kt, int tid)
{
    uint32_t As = smem_base + s * STG;
    uint32_t Bs = As + 16384;
    int koff = kt * 64;
    #pragma unroll
    for (int it = 0; it < 4; it++) {
        int i = tid + it * 256;
        int r = i >> 3, c8 = i & 7;
        cp16(As + r * 128 + ((c8 ^ (r & 7)) << 4), Ap + (size_t)r * 512 + koff + c8 * 8);
    }
    #pragma unroll
    for (int it = 0; it < 4; it++) {
        int i = tid + it * 256;
        int r = i >> 3, c8 = i & 7;
        cp16(Bs + r * 128 + ((c8 ^ (r & 7)) << 4), Bp + (size_t)r * 512 + koff + c8 * 8);
    }
    cp_commit();
}

template<int MODE>
__global__ __launch_bounds__(256, 2)
void gemm_f16(const __half* __restrict__ A, const __half* __restrict__ Bw,
              const float* __restrict__ bq, const float* __restrict__ bk,
              const float* __restrict__ bv,
              void* __restrict__ dq, void* __restrict__ dk_, void* __restrict__ dv)
{
    extern __shared__ char sm[];
    const int tid = threadIdx.x, wid = tid >> 5, lane = tid & 31;
    const int g = lane >> 2, tg = lane & 3;
    const int n0 = blockIdx.x * 128, m0 = blockIdx.y * 128;
    const int wm = (wid & 3) * 32, wn = (wid >> 2) * 64;

    uint32_t sbase = smem_u32(sm);
    const __half* Ap = A + (size_t)m0 * 512;
    const __half* Bp = Bw + (size_t)n0 * 512;

    float acc[2][8][4];
    #pragma unroll
    for (int a = 0; a < 2; a++)
        #pragma unroll
        for (int b = 0; b < 8; b++)
            #pragma unroll
            for (int c = 0; c < 4; c++) acc[a][b][c] = 0.f;

    fill_stage(sbase, 0, Ap, Bp, 0, tid);
    fill_stage(sbase, 1, Ap, Bp, 1, tid);

    for (int kt = 0; kt < 8; kt++) {
        if (kt < 7) asm volatile("cp.async.wait_group 1;" ::: "memory");
        else        asm volatile("cp.async.wait_group 0;" ::: "memory");
        __syncthreads();
        if (kt + 2 < 8) fill_stage(sbase, (kt + 2) % 3, Ap, Bp, kt + 2, tid);

        char* As = sm + (kt % 3) * STG;
        char* Bs = As + 16384;

        #pragma unroll
        for (int ks = 0; ks < 4; ks++) {
            int c0 = ks * 2;
            uint32_t af[2][4], bf[8][2];
            #pragma unroll
            for (int im = 0; im < 2; im++) {
                int r = wm + im * 16 + g;
                char* p0 = As + r * 128 + 4 * tg;
                char* p1 = As + (r + 8) * 128 + 4 * tg;
                af[im][0] = *(uint32_t*)(p0 + ((c0       ^ g) << 4));
                af[im][1] = *(uint32_t*)(p1 + ((c0       ^ g) << 4));
                af[im][2] = *(uint32_t*)(p0 + (((c0 + 1) ^ g) << 4));
                af[im][3] = *(uint32_t*)(p1 + (((c0 + 1) ^ g) << 4));
            }
            #pragma unroll
            for (int in = 0; in < 8; in++) {
                int n = wn + in * 8 + g;
                char* p = Bs + n * 128 + 4 * tg;
                bf[in][0] = *(uint32_t*)(p + ((c0       ^ g) << 4));
                bf[in][1] = *(uint32_t*)(p + (((c0 + 1) ^ g) << 4));
            }
            #pragma unroll
            for (int im = 0; im < 2; im++)
                #pragma unroll
                for (int in = 0; in < 8; in++)
                    mma_f16(acc[im][in], af[im][0], af[im][1], af[im][2], af[im][3],
                            bf[in][0], bf[in][1]);
        }
        __syncthreads();
    }

    if (MODE == 0) {
        // pick tensor + bias by n-block
        int t = n0 >> 9, nc0 = n0 & 511, h0 = nc0 >> 6;
        const float* bias = (t == 0 ? bq : t == 1 ? bk : bv) + nc0;
        __half* dst_t = (__half*)(t == 0 ? dq : t == 1 ? dk_ : dv);

        // acc (+bias) -> smem fp16 tile Cs[128][136]
        #pragma unroll
        for (int im = 0; im < 2; im++) {
            #pragma unroll
            for (int in = 0; in < 8; in++) {
                int col = wn + in * 8 + 2 * tg;
                float bb0 = bias[col], bb1 = bias[col + 1];
                int r0 = wm + im * 16 + g;
                *(__half2*)(sm + r0 * 272 + col * 2) =
                    __floats2half2_rn(acc[im][in][0] + bb0, acc[im][in][1] + bb1);
                *(__half2*)(sm + (r0 + 8) * 272 + col * 2) =
                    __floats2half2_rn(acc[im][in][2] + bb0, acc[im][in][3] + bb1);
            }
        }
        __syncthreads();

        // coalesced stores: thread = (m, h-block); 64 contiguous halves each
        int m = tid >> 1, hb = tid & 1;
        int r = m0 + m, bt = r >> 6, mm = r & 63;
        __half* dst = dst_t + (((size_t)(bt * 8 + h0 + hb) * 64 + mm) * 64);
        const uint4* srcp = (const uint4*)(sm + m * 272 + hb * 128);
        uint4* dstp = (uint4*)dst;
        #pragma unroll
        for (int j = 0; j < 8; j++) dstp[j] = srcp[j];
    } else {
        // direct fp32 stores
        float* out = (float*)dq;
        const float* bias = bq;
        #pragma unroll
        for (int im = 0; im < 2; im++) {
            #pragma unroll
            for (int in = 0; in < 8; in++) {
                int col = n0 + wn + in * 8 + 2 * tg;
                float bb0 = bias[col], bb1 = bias[col + 1];
                int r0 = m0 + wm + im * 16 + g;
                float2 v0 = {acc[im][in][0] + bb0, acc[im][in][1] + bb1};
                float2 v1 = {acc[im][in][2] + bb0, acc[im][in][3] + bb1};
                *(float2*)(out + (size_t)r0 * 512 + col) = v0;
                *(float2*)(out + (size_t)(r0 + 8) * 512 + col) = v1;
            }
        }
    }
}

// ---------------------------------------------------------------------------
// Attention v2: 2048 CTAs x 8 tiles, cp.async double-buffered prefetch.
// Per tile: scores = q@k^T/8 -> softmax -> p@v -> staged coalesced store.
// smem layout (halves): buf0 {q 64x72, k 64x72, vraw 64x64} = 13312,
//                       buf1 same = 13312, vt 64x72 = 4608, ss 64x72 = 4608.
// Total 35840 halves = 71680 bytes.
// ---------------------------------------------------------------------------
#define ATT_TILES 8
#define ABUF_H 13312
#define ATT_SMEM 71680

__global__ __launch_bounds__(128)
void attn_kernel()
{
    extern __shared__ __half smh[];
    const int tid = threadIdx.x;
    const int w = tid >> 5, lane = tid & 31;
    const int g = lane >> 2, tg = lane & 3;
    const int mr = w * 16;

    __half* vt = smh + 2 * ABUF_H;
    __half* ss = vt + 4608;
    const uint32_t sb = smem_u32(smh);
    const int bth0 = blockIdx.x * ATT_TILES;

    auto prefetch = [&](int buf, int bth) {
        const __half* qg = g_q + (size_t)bth * 4096;
        const __half* kg = g_k + (size_t)bth * 4096;
        const __half* vg = g_v + (size_t)bth * 4096;
        uint32_t q0 = sb + buf * (ABUF_H * 2);
        uint32_t k0 = q0 + 9216;
        uint32_t v0 = k0 + 9216;
        #pragma unroll
        for (int it = 0; it < 4; it++) {
            int i = tid + it * 128;
            int r = i >> 3, c8 = i & 7;
            cp16(q0 + r * 144 + c8 * 16, qg + r * 64 + c8 * 8);
            cp16(k0 + r * 144 + c8 * 16, kg + r * 64 + c8 * 8);
            cp16(v0 + r * 128 + c8 * 16, vg + r * 64 + c8 * 8);
        }
        cp_commit();
    };

    prefetch(0, bth0);

    for (int t = 0; t < ATT_TILES; t++) {
        const int bth = bth0 + t;
        if (t + 1 < ATT_TILES) {
            prefetch((t + 1) & 1, bth + 1);
            asm volatile("cp.async.wait_group 1;" ::: "memory");
        } else {
            asm volatile("cp.async.wait_group 0;" ::: "memory");
        }
        __syncthreads();      // tile t resident; all warps done with prior tile

        __half* qs   = smh + (t & 1) * ABUF_H;
        __half* ks_  = qs + 4608;
        __half* vraw = ks_ + 4608;

        // transpose vraw[m][dk] -> vt[dk][m]
        #pragma unroll
        for (int it = 0; it < 4; it++) {
            int i = tid + it * 128;
            int r = i >> 3, c8 = i & 7;
            uint4 vv = *(const uint4*)(vraw + r * 64 + c8 * 8);
            const __half* hv = (const __half*)&vv;
            #pragma unroll
            for (int j = 0; j < 8; j++) vt[(c8 * 8 + j) * 72 + r] = hv[j];
        }

        float c[8][4];
        #pragma unroll
        for (int in = 0; in < 8; in++)
            #pragma unroll
            for (int j = 0; j < 4; j++) c[in][j] = 0.f;

        // scores = q @ k^T
        #pragma unroll
        for (int ks4 = 0; ks4 < 4; ks4++) {
            int koff = ks4 * 16;
            uint32_t a0 = *(uint32_t*)(qs + (mr + g    ) * 72 + koff + 2 * tg);
            uint32_t a1 = *(uint32_t*)(qs + (mr + g + 8) * 72 + koff + 2 * tg);
            uint32_t a2 = *(uint32_t*)(qs + (mr + g    ) * 72 + koff + 2 * tg + 8);
            uint32_t a3 = *(uint32_t*)(qs + (mr + g + 8) * 72 + koff + 2 * tg + 8);
            #pragma unroll
            for (int in = 0; in < 8; in++) {
                int nr = in * 8 + g;
                uint32_t b0 = *(uint32_t*)(ks_ + nr * 72 + koff + 2 * tg);
                uint32_t b1 = *(uint32_t*)(ks_ + nr * 72 + koff + 2 * tg + 8);
                mma_f16(c[in], a0, a1, a2, a3, b0, b1);
            }
        }

        // softmax (scale 1/8)
        const float scale = 0.125f;
        float mx0 = -1e30f, mx1 = -1e30f;
        #pragma unroll
        for (int in = 0; in < 8; in++) {
            c[in][0] *= scale; c[in][1] *= scale;
            c[in][2] *= scale; c[in][3] *= scale;
            mx0 = fmaxf(mx0, fmaxf(c[in][0], c[in][1]));
            mx1 = fmaxf(mx1, fmaxf(c[in][2], c[in][3]));
        }
        mx0 = fmaxf(mx0, __shfl_xor_sync(0xffffffffu, mx0, 1));
        mx0 = fmaxf(mx0, __shfl_xor_sync(0xffffffffu, mx0, 2));
        mx1 = fmaxf(mx1, __shfl_xor_sync(0xffffffffu, mx1, 1));
        mx1 = fmaxf(mx1, __shfl_xor_sync(0xffffffffu, mx1, 2));

        float s0 = 0.f, s1 = 0.f;
        #pragma unroll
        for (int in = 0; in < 8; in++) {
            c[in][0] = __expf(c[in][0] - mx0); s0 += c[in][0];
            c[in][1] = __expf(c[in][1] - mx0); s0 += c[in][1];
            c[in][2] = __expf(c[in][2] - mx1); s1 += c[in][2];
            c[in][3] = __expf(c[in][3] - mx1); s1 += c[in][3];
        }
        s0 += __shfl_xor_sync(0xffffffffu, s0, 1);
        s0 += __shfl_xor_sync(0xffffffffu, s0, 2);
        s1 += __shfl_xor_sync(0xffffffffu, s1, 1);
        s1 += __shfl_xor_sync(0xffffffffu, s1, 2);
        float inv0 = 1.f / s0, inv1 = 1.f / s1;

        // write P (own warp rows)
        #pragma unroll
        for (int in = 0; in < 8; in++) {
            int col = in * 8 + 2 * tg;
            *(__half2*)(ss + (mr + g    ) * 72 + col) = __floats2half2_rn(c[in][0] * inv0, c[in][1] * inv0);
            *(__half2*)(ss + (mr + g + 8) * 72 + col) = __floats2half2_rn(c[in][2] * inv1, c[in][3] * inv1);
        }
        __syncthreads();    // vt complete (and P visible within warp rows)

        #pragma unroll
        for (int in = 0; in < 8; in++)
            #pragma unroll
            for (int j = 0; j < 4; j++) c[in][j] = 0.f;

        // out = P @ V   (A = ss[m][m'] own rows, B[k=m'][n=dk] = vt[dk][m'])
        #pragma unroll
        for (int ks4 = 0; ks4 < 4; ks4++) {
            int koff = ks4 * 16;
            uint32_t a0 = *(uint32_t*)(ss + (mr + g    ) * 72 + koff + 2 * tg);
            uint32_t a1 = *(uint32_t*)(ss + (mr + g + 8) * 72 + koff + 2 * tg);
            uint32_t a2 = *(uint32_t*)(ss + (mr + g    ) * 72 + koff + 2 * tg + 8);
            uint32_t a3 = *(uint32_t*)(ss + (mr + g + 8) * 72 + koff + 2 * tg + 8);
            #pragma unroll
            for (int in = 0; in < 8; in++) {
                int nr = in * 8 + g;
                uint32_t b0 = *(uint32_t*)(vt + nr * 72 + koff + 2 * tg);
                uint32_t b1 = *(uint32_t*)(vt + nr * 72 + koff + 2 * tg + 8);
                mma_f16(c[in], a0, a1, a2, a3, b0, b1);
            }
        }

        // stage output tile into ss (own warp rows; own P reads already done)
        #pragma unroll
        for (int in = 0; in < 8; in++) {
            int col = in * 8 + 2 * tg;
            *(__half2*)(ss + (mr + g    ) * 72 + col) = __floats2half2_rn(c[in][0], c[in][1]);
            *(__half2*)(ss + (mr + g + 8) * 72 + col) = __floats2half2_rn(c[in][2], c[in][3]);
        }
        __syncthreads();

        // coalesced store: 2 threads per row, 64B each -> full 128B segments
        {
            const int bt = bth >> 3, h = bth & 7;
            __half* dst = g_a + ((size_t)bt * 64) * 512 + h * 64;
            int row = tid >> 1, part = tid & 1;
            const uint4* sp = (const uint4*)(ss + row * 72 + part * 32);
            uint4* dp = (uint4*)(dst + (size_t)row * 512 + part * 32);
            dp[0] = sp[0]; dp[1] = sp[1]; dp[2] = sp[2]; dp[3] = sp[3];
        }
    }
}

// ---------------------------------------------------------------------------
extern "C" void kernel_launch(void* const* d_in, const int* in_sizes, int n_in,
                              void* d_out, int out_size)
{
    const float* x  = (const float*)d_in[0];
    const float* Wq = (const float*)d_in[1];
    const float* bq = (const float*)d_in[2];
    const float* Wk = (const float*)d_in[3];
    const float* bk = (const float*)d_in[4];
    const float* Wv = (const float*)d_in[5];
    const float* bv = (const float*)d_in[6];
    const float* Wo = (const float*)d_in[7];
    const float* bo = (const float*)d_in[8];
    float* out = (float*)d_out;

    void *pxh, *pwqkv, *pwo, *pq, *pk, *pv, *pa;
    cudaGetSymbolAddress(&pxh,   g_xh);
    cudaGetSymbolAddress(&pwqkv, g_wqkv);
    cudaGetSymbolAddress(&pwo,   g_wo);
    cudaGetSymbolAddress(&pq,    g_q);
    cudaGetSymbolAddress(&pk,    g_k);
    cudaGetSymbolAddress(&pv,    g_v);
    cudaGetSymbolAddress(&pa,    g_a);
    __half* wqkv = (__half*)pwqkv;

    // 1) fp32 -> fp16 conversions
    conv_h<<<(NROWS*DD/4 + 255)/256, 256>>>((const float4*)x, (uint2*)pxh, NROWS*DD/4);
    conv_w<<<(4*DD*DD/4 + 255)/256, 256>>>((const float4*)Wq, (const float4*)Wk,
                                           (const float4*)Wv, (const float4*)Wo,
                                           (uint2*)pwqkv, (uint2*)pwo);

    cudaFuncSetAttribute(gemm_f16<0>, cudaFuncAttributeMaxDynamicSharedMemorySize, GEMM_SMEM);
    cudaFuncSetAttribute(gemm_f16<1>, cudaFuncAttributeMaxDynamicSharedMemorySize, GEMM_SMEM);
    cudaFuncSetAttribute(attn_kernel, cudaFuncAttributeMaxDynamicSharedMemorySize, ATT_SMEM);

    // 2) fused QKV projection: N = 1536
    dim3 gqkv(12, NROWS / 128);
    gemm_f16<0><<<gqkv, 256, GEMM_SMEM>>>((const __half*)pxh, wqkv,
                                          bq, bk, bv, pq, pk, pv);

    // 3) attention (2048 CTAs x 8 tiles, double-buffered)
    attn_kernel<<<NBTH / ATT_TILES, 128, ATT_SMEM>>>();

    // 4) output projection: N = 512, fp32 out
    dim3 go(4, NROWS / 128);
    gemm_f16<1><<<go, 256, GEMM_SMEM>>>((const __half*)pa, (const __half*)pwo,
                                        bo, nullptr, nullptr, out, nullptr, nullptr);
}

// round 6
// speedup vs baseline: 1.6104x; 1.1056x over previous
#include <cuda_runtime.h>
#include <cuda_fp16.h>
#include <cstdint>

// Problem constants
#define BB 8
#define TT 256
#define MM 64
#define DD 512
#define HH 8
#define DKK 64
#define NROWS (BB*TT*MM)        // 131072
#define NBTH  (BB*TT*HH)        // 16384

// Scratch (device globals: allocation-free)
__device__ __half g_xh[(size_t)NROWS*DD];      // X in fp16
__device__ __half g_wqkv[3*DD*DD];             // packed Wq|Wk|Wv fp16 (rows = features)
__device__ __half g_wo[DD*DD];                 // Wo fp16
__device__ __half g_q[(size_t)NBTH*MM*DKK];    // (bt,h,m,dk) fp16
__device__ __half g_k[(size_t)NBTH*MM*DKK];
__device__ __half g_v[(size_t)NBTH*MM*DKK];
__device__ __half g_a[(size_t)NROWS*DD];       // (btm, d) fp16 attention output

__device__ __forceinline__ uint32_t smem_u32(const void* p) {
    uint32_t a;
    asm("{ .reg .u64 t; cvta.to.shared.u64 t, %1; cvt.u32.u64 %0, t; }" : "=r"(a) : "l"(p));
    return a;
}
__device__ __forceinline__ void cp16(uint32_t saddr, const void* gaddr) {
    asm volatile("cp.async.cg.shared.global [%0], [%1], 16;" :: "r"(saddr), "l"(gaddr) : "memory");
}
__device__ __forceinline__ void cp_commit() {
    asm volatile("cp.async.commit_group;" ::: "memory");
}

__device__ __forceinline__ void mma_f16(float* c,
    uint32_t a0, uint32_t a1, uint32_t a2, uint32_t a3, uint32_t b0, uint32_t b1)
{
    asm volatile(
        "mma.sync.aligned.m16n8k16.row.col.f32.f16.f16.f32 "
        "{%0,%1,%2,%3}, {%4,%5,%6,%7}, {%8,%9}, {%0,%1,%2,%3};"
        : "+f"(c[0]), "+f"(c[1]), "+f"(c[2]), "+f"(c[3])
        : "r"(a0), "r"(a1), "r"(a2), "r"(a3), "r"(b0), "r"(b1));
}

// ---------------------------------------------------------------------------
// conv kernels: fp32 -> fp16
// ---------------------------------------------------------------------------
__global__ void conv_h(const float4* __restrict__ in, uint2* __restrict__ out, int n4)
{
    int i = blockIdx.x * blockDim.x + threadIdx.x;
    if (i >= n4) return;
    float4 v = in[i];
    __half2 h0 = __floats2half2_rn(v.x, v.y);
    __half2 h1 = __floats2half2_rn(v.z, v.w);
    uint2 r;
    r.x = *(uint32_t*)&h0;
    r.y = *(uint32_t*)&h1;
    out[i] = r;
}

__global__ void conv_w(const float4* __restrict__ wq, const float4* __restrict__ wk,
                       const float4* __restrict__ wv, const float4* __restrict__ wo,
                       uint2* __restrict__ oqkv, uint2* __restrict__ oo)
{
    int i = blockIdx.x * blockDim.x + threadIdx.x;   // 0 .. 4*65536-1
    int t = i >> 16, j = i & 65535;
    const float4* src = (t == 0) ? wq : (t == 1) ? wk : (t == 2) ? wv : wo;
    uint2* dst = (t == 3) ? oo : (oqkv + (size_t)t * (DD*DD/4));
    float4 v = src[j];
    __half2 h0 = __floats2half2_rn(v.x, v.y);
    __half2 h1 = __floats2half2_rn(v.z, v.w);
    uint2 r;
    r.x = *(uint32_t*)&h0;
    r.y = *(uint32_t*)&h1;
    dst[j] = r;
}

// ---------------------------------------------------------------------------
// fp16 GEMM v2: D[128 x 128] block of Y = A(rows,512) @ B(cols,512)^T
// 3-stage cp.async pipeline, BK=64, XOR-swizzled 128B smem rows, scalar LDS.
// 4 warps (2x2), warp tile 64x64 -> 16 MAC/byte crossbar intensity,
// 128 independent acc chains per warp.
// ---------------------------------------------------------------------------
#define STG 32768                 // per-stage bytes: A 16KB + B 16KB
#define GEMM_SMEM (3*STG)

__device__ __forceinline__ void fill_stage(uint32_t smem_base, int s,
                                           const __half* __restrict__ Ap,
                                           const __half* __restrict__ Bp,
                                           int kt, int tid)
{
    uint32_t As = smem_base + s * STG;
    uint32_t Bs = As + 16384;
    int koff = kt * 64;
    #pragma unroll
    for (int it = 0; it < 8; it++) {
        int i = tid + it * 128;
        int r = i >> 3, c8 = i & 7;
        cp16(As + r * 128 + ((c8 ^ (r & 7)) << 4), Ap + (size_t)r * 512 + koff + c8 * 8);
    }
    #pragma unroll
    for (int it = 0; it < 8; it++) {
        int i = tid + it * 128;
        int r = i >> 3, c8 = i & 7;
        cp16(Bs + r * 128 + ((c8 ^ (r & 7)) << 4), Bp + (size_t)r * 512 + koff + c8 * 8);
    }
    cp_commit();
}

template<int MODE>
__global__ __launch_bounds__(128, 2)
void gemm_f16(const __half* __restrict__ A, const __half* __restrict__ Bw,
              const float* __restrict__ bq, const float* __restrict__ bk,
              const float* __restrict__ bv,
              void* __restrict__ dq, void* __restrict__ dk_, void* __restrict__ dv)
{
    extern __shared__ char sm[];
    const int tid = threadIdx.x, wid = tid >> 5, lane = tid & 31;
    const int g = lane >> 2, tg = lane & 3;
    const int n0 = blockIdx.x * 128, m0 = blockIdx.y * 128;
    const int wm = (wid & 1) * 64, wn = (wid >> 1) * 64;

    uint32_t sbase = smem_u32(sm);
    const __half* Ap = A + (size_t)m0 * 512;
    const __half* Bp = Bw + (size_t)n0 * 512;

    float acc[4][8][4];
    #pragma unroll
    for (int a = 0; a < 4; a++)
        #pragma unroll
        for (int b = 0; b < 8; b++)
            #pragma unroll
            for (int c = 0; c < 4; c++) acc[a][b][c] = 0.f;

    fill_stage(sbase, 0, Ap, Bp, 0, tid);
    fill_stage(sbase, 1, Ap, Bp, 1, tid);

    for (int kt = 0; kt < 8; kt++) {
        if (kt < 7) asm volatile("cp.async.wait_group 1;" ::: "memory");
        else        asm volatile("cp.async.wait_group 0;" ::: "memory");
        __syncthreads();
        if (kt + 2 < 8) fill_stage(sbase, (kt + 2) % 3, Ap, Bp, kt + 2, tid);

        char* As = sm + (kt % 3) * STG;
        char* Bs = As + 16384;

        #pragma unroll
        for (int ks = 0; ks < 4; ks++) {
            int c0 = ks * 2;
            int sel0 = (c0 ^ g) << 4, sel1 = ((c0 + 1) ^ g) << 4;
            uint32_t af[4][4], bf[8][2];
            #pragma unroll
            for (int im = 0; im < 4; im++) {
                int r = wm + im * 16 + g;
                char* p0 = As + r * 128 + 4 * tg;
                char* p1 = As + (r + 8) * 128 + 4 * tg;
                af[im][0] = *(uint32_t*)(p0 + sel0);
                af[im][1] = *(uint32_t*)(p1 + sel0);
                af[im][2] = *(uint32_t*)(p0 + sel1);
                af[im][3] = *(uint32_t*)(p1 + sel1);
            }
            #pragma unroll
            for (int in = 0; in < 8; in++) {
                int n = wn + in * 8 + g;
                char* p = Bs + n * 128 + 4 * tg;
                bf[in][0] = *(uint32_t*)(p + sel0);
                bf[in][1] = *(uint32_t*)(p + sel1);
            }
            #pragma unroll
            for (int im = 0; im < 4; im++)
                #pragma unroll
                for (int in = 0; in < 8; in++)
                    mma_f16(acc[im][in], af[im][0], af[im][1], af[im][2], af[im][3],
                            bf[in][0], bf[in][1]);
        }
        __syncthreads();
    }

    if (MODE == 0) {
        // pick tensor + bias by n-block
        int t = n0 >> 9, nc0 = n0 & 511, h0 = nc0 >> 6;
        const float* bias = (t == 0 ? bq : t == 1 ? bk : bv) + nc0;
        __half* dst_t = (__half*)(t == 0 ? dq : t == 1 ? dk_ : dv);

        // acc (+bias) -> smem fp16 tile Cs[128][136]
        #pragma unroll
        for (int im = 0; im < 4; im++) {
            #pragma unroll
            for (int in = 0; in < 8; in++) {
                int col = wn + in * 8 + 2 * tg;
                float bb0 = bias[col], bb1 = bias[col + 1];
                int r0 = wm + im * 16 + g;
                *(__half2*)(sm + r0 * 272 + col * 2) =
                    __floats2half2_rn(acc[im][in][0] + bb0, acc[im][in][1] + bb1);
                *(__half2*)(sm + (r0 + 8) * 272 + col * 2) =
                    __floats2half2_rn(acc[im][in][2] + bb0, acc[im][in][3] + bb1);
            }
        }
        __syncthreads();

        // coalesced stores: thread = row; 2 h-blocks of 64 contiguous halves
        int m = tid;
        int r = m0 + m, bt = r >> 6, mm = r & 63;
        #pragma unroll
        for (int hb = 0; hb < 2; hb++) {
            __half* dst = dst_t + (((size_t)(bt * 8 + h0 + hb) * 64 + mm) * 64);
            const uint4* srcp = (const uint4*)(sm + m * 272 + hb * 128);
            uint4* dstp = (uint4*)dst;
            #pragma unroll
            for (int j = 0; j < 8; j++) dstp[j] = srcp[j];
        }
    } else {
        // direct fp32 stores
        float* out = (float*)dq;
        const float* bias = bq;
        #pragma unroll
        for (int im = 0; im < 4; im++) {
            #pragma unroll
            for (int in = 0; in < 8; in++) {
                int col = n0 + wn + in * 8 + 2 * tg;
                float bb0 = bias[col], bb1 = bias[col + 1];
                int r0 = m0 + wm + im * 16 + g;
                float2 v0 = {acc[im][in][0] + bb0, acc[im][in][1] + bb1};
                float2 v1 = {acc[im][in][2] + bb0, acc[im][in][3] + bb1};
                *(float2*)(out + (size_t)r0 * 512 + col) = v0;
                *(float2*)(out + (size_t)(r0 + 8) * 512 + col) = v1;
            }
        }
    }
}

// ---------------------------------------------------------------------------
// Attention v2 (R5-proven): 2048 CTAs x 8 tiles, cp.async double-buffered.
// ---------------------------------------------------------------------------
#define ATT_TILES 8
#define ABUF_H 13312
#define ATT_SMEM 71680

__global__ __launch_bounds__(128)
void attn_kernel()
{
    extern __shared__ __half smh[];
    const int tid = threadIdx.x;
    const int w = tid >> 5, lane = tid & 31;
    const int g = lane >> 2, tg = lane & 3;
    const int mr = w * 16;

    __half* vt = smh + 2 * ABUF_H;
    __half* ss = vt + 4608;
    const uint32_t sb = smem_u32(smh);
    const int bth0 = blockIdx.x * ATT_TILES;

    auto prefetch = [&](int buf, int bth) {
        const __half* qg = g_q + (size_t)bth * 4096;
        const __half* kg = g_k + (size_t)bth * 4096;
        const __half* vg = g_v + (size_t)bth * 4096;
        uint32_t q0 = sb + buf * (ABUF_H * 2);
        uint32_t k0 = q0 + 9216;
        uint32_t v0 = k0 + 9216;
        #pragma unroll
        for (int it = 0; it < 4; it++) {
            int i = tid + it * 128;
            int r = i >> 3, c8 = i & 7;
            cp16(q0 + r * 144 + c8 * 16, qg + r * 64 + c8 * 8);
            cp16(k0 + r * 144 + c8 * 16, kg + r * 64 + c8 * 8);
            cp16(v0 + r * 128 + c8 * 16, vg + r * 64 + c8 * 8);
        }
        cp_commit();
    };

    prefetch(0, bth0);

    for (int t = 0; t < ATT_TILES; t++) {
        const int bth = bth0 + t;
        if (t + 1 < ATT_TILES) {
            prefetch((t + 1) & 1, bth + 1);
            asm volatile("cp.async.wait_group 1;" ::: "memory");
        } else {
            asm volatile("cp.async.wait_group 0;" ::: "memory");
        }
        __syncthreads();      // tile t resident; all warps done with prior tile

        __half* qs   = smh + (t & 1) * ABUF_H;
        __half* ks_  = qs + 4608;
        __half* vraw = ks_ + 4608;

        // transpose vraw[m][dk] -> vt[dk][m]
        #pragma unroll
        for (int it = 0; it < 4; it++) {
            int i = tid + it * 128;
            int r = i >> 3, c8 = i & 7;
            uint4 vv = *(const uint4*)(vraw + r * 64 + c8 * 8);
            const __half* hv = (const __half*)&vv;
            #pragma unroll
            for (int j = 0; j < 8; j++) vt[(c8 * 8 + j) * 72 + r] = hv[j];
        }

        float c[8][4];
        #pragma unroll
        for (int in = 0; in < 8; in++)
            #pragma unroll
            for (int j = 0; j < 4; j++) c[in][j] = 0.f;

        // scores = q @ k^T
        #pragma unroll
        for (int ks4 = 0; ks4 < 4; ks4++) {
            int koff = ks4 * 16;
            uint32_t a0 = *(uint32_t*)(qs + (mr + g    ) * 72 + koff + 2 * tg);
            uint32_t a1 = *(uint32_t*)(qs + (mr + g + 8) * 72 + koff + 2 * tg);
            uint32_t a2 = *(uint32_t*)(qs + (mr + g    ) * 72 + koff + 2 * tg + 8);
            uint32_t a3 = *(uint32_t*)(qs + (mr + g + 8) * 72 + koff + 2 * tg + 8);
            #pragma unroll
            for (int in = 0; in < 8; in++) {
                int nr = in * 8 + g;
                uint32_t b0 = *(uint32_t*)(ks_ + nr * 72 + koff + 2 * tg);
                uint32_t b1 = *(uint32_t*)(ks_ + nr * 72 + koff + 2 * tg + 8);
                mma_f16(c[in], a0, a1, a2, a3, b0, b1);
            }
        }

        // softmax (scale 1/8)
        const float scale = 0.125f;
        float mx0 = -1e30f, mx1 = -1e30f;
        #pragma unroll
        for (int in = 0; in < 8; in++) {
            c[in][0] *= scale; c[in][1] *= scale;
            c[in][2] *= scale; c[in][3] *= scale;
            mx0 = fmaxf(mx0, fmaxf(c[in][0], c[in][1]));
            mx1 = fmaxf(mx1, fmaxf(c[in][2], c[in][3]));
        }
        mx0 = fmaxf(mx0, __shfl_xor_sync(0xffffffffu, mx0, 1));
        mx0 = fmaxf(mx0, __shfl_xor_sync(0xffffffffu, mx0, 2));
        mx1 = fmaxf(mx1, __shfl_xor_sync(0xffffffffu, mx1, 1));
        mx1 = fmaxf(mx1, __shfl_xor_sync(0xffffffffu, mx1, 2));

        float s0 = 0.f, s1 = 0.f;
        #pragma unroll
        for (int in = 0; in < 8; in++) {
            c[in][0] = __expf(c[in][0] - mx0); s0 += c[in][0];
            c[in][1] = __expf(c[in][1] - mx0); s0 += c[in][1];
            c[in][2] = __expf(c[in][2] - mx1); s1 += c[in][2];
            c[in][3] = __expf(c[in][3] - mx1); s1 += c[in][3];
        }
        s0 += __shfl_xor_sync(0xffffffffu, s0, 1);
        s0 += __shfl_xor_sync(0xffffffffu, s0, 2);
        s1 += __shfl_xor_sync(0xffffffffu, s1, 1);
        s1 += __shfl_xor_sync(0xffffffffu, s1, 2);
        float inv0 = 1.f / s0, inv1 = 1.f / s1;

        // write P (own warp rows)
        #pragma unroll
        for (int in = 0; in < 8; in++) {
            int col = in * 8 + 2 * tg;
            *(__half2*)(ss + (mr + g    ) * 72 + col) = __floats2half2_rn(c[in][0] * inv0, c[in][1] * inv0);
            *(__half2*)(ss + (mr + g + 8) * 72 + col) = __floats2half2_rn(c[in][2] * inv1, c[in][3] * inv1);
        }
        __syncthreads();    // vt complete (and P visible within warp rows)

        #pragma unroll
        for (int in = 0; in < 8; in++)
            #pragma unroll
            for (int j = 0; j < 4; j++) c[in][j] = 0.f;

        // out = P @ V   (A = ss[m][m'] own rows, B[k=m'][n=dk] = vt[dk][m'])
        #pragma unroll
        for (int ks4 = 0; ks4 < 4; ks4++) {
            int koff = ks4 * 16;
            uint32_t a0 = *(uint32_t*)(ss + (mr + g    ) * 72 + koff + 2 * tg);
            uint32_t a1 = *(uint32_t*)(ss + (mr + g + 8) * 72 + koff + 2 * tg);
            uint32_t a2 = *(uint32_t*)(ss + (mr + g    ) * 72 + koff + 2 * tg + 8);
            uint32_t a3 = *(uint32_t*)(ss + (mr + g + 8) * 72 + koff + 2 * tg + 8);
            #pragma unroll
            for (int in = 0; in < 8; in++) {
                int nr = in * 8 + g;
                uint32_t b0 = *(uint32_t*)(vt + nr * 72 + koff + 2 * tg);
                uint32_t b1 = *(uint32_t*)(vt + nr * 72 + koff + 2 * tg + 8);
                mma_f16(c[in], a0, a1, a2, a3, b0, b1);
            }
        }

        // stage output tile into ss (own warp rows; own P reads already done)
        #pragma unroll
        for (int in = 0; in < 8; in++) {
            int col = in * 8 + 2 * tg;
            *(__half2*)(ss + (mr + g    ) * 72 + col) = __floats2half2_rn(c[in][0], c[in][1]);
            *(__half2*)(ss + (mr + g + 8) * 72 + col) = __floats2half2_rn(c[in][2], c[in][3]);
        }
        __syncthreads();

        // coalesced store: 2 threads per row, 64B each -> full 128B segments
        {
            const int bt = bth >> 3, h = bth & 7;
            __half* dst = g_a + ((size_t)bt * 64) * 512 + h * 64;
            int row = tid >> 1, part = tid & 1;
            const uint4* sp = (const uint4*)(ss + row * 72 + part * 32);
            uint4* dp = (uint4*)(dst + (size_t)row * 512 + part * 32);
            dp[0] = sp[0]; dp[1] = sp[1]; dp[2] = sp[2]; dp[3] = sp[3];
        }
    }
}

// ---------------------------------------------------------------------------
extern "C" void kernel_launch(void* const* d_in, const int* in_sizes, int n_in,
                              void* d_out, int out_size)
{
    const float* x  = (const float*)d_in[0];
    const float* Wq = (const float*)d_in[1];
    const float* bq = (const float*)d_in[2];
    const float* Wk = (const float*)d_in[3];
    const float* bk = (const float*)d_in[4];
    const float* Wv = (const float*)d_in[5];
    const float* bv = (const float*)d_in[6];
    const float* Wo = (const float*)d_in[7];
    const float* bo = (const float*)d_in[8];
    float* out = (float*)d_out;

    void *pxh, *pwqkv, *pwo, *pq, *pk, *pv, *pa;
    cudaGetSymbolAddress(&pxh,   g_xh);
    cudaGetSymbolAddress(&pwqkv, g_wqkv);
    cudaGetSymbolAddress(&pwo,   g_wo);
    cudaGetSymbolAddress(&pq,    g_q);
    cudaGetSymbolAddress(&pk,    g_k);
    cudaGetSymbolAddress(&pv,    g_v);
    cudaGetSymbolAddress(&pa,    g_a);
    __half* wqkv = (__half*)pwqkv;

    // 1) fp32 -> fp16 conversions
    conv_h<<<(NROWS*DD/4 + 255)/256, 256>>>((const float4*)x, (uint2*)pxh, NROWS*DD/4);
    conv_w<<<(4*DD*DD/4 + 255)/256, 256>>>((const float4*)Wq, (const float4*)Wk,
                                           (const float4*)Wv, (const float4*)Wo,
                                           (uint2*)pwqkv, (uint2*)pwo);

    cudaFuncSetAttribute(gemm_f16<0>, cudaFuncAttributeMaxDynamicSharedMemorySize, GEMM_SMEM);
    cudaFuncSetAttribute(gemm_f16<1>, cudaFuncAttributeMaxDynamicSharedMemorySize, GEMM_SMEM);
    cudaFuncSetAttribute(attn_kernel, cudaFuncAttributeMaxDynamicSharedMemorySize, ATT_SMEM);

    // 2) fused QKV projection: N = 1536
    dim3 gqkv(12, NROWS / 128);
    gemm_f16<0><<<gqkv, 128, GEMM_SMEM>>>((const __half*)pxh, wqkv,
                                          bq, bk, bv, pq, pk, pv);

    // 3) attention (2048 CTAs x 8 tiles, double-buffered)
    attn_kernel<<<NBTH / ATT_TILES, 128, ATT_SMEM>>>();

    // 4) output projection: N = 512, fp32 out
    dim3 go(4, NROWS / 128);
    gemm_f16<1><<<go, 128, GEMM_SMEM>>>((const __half*)pa, (const __half*)pwo,
                                        bo, nullptr, nullptr, out, nullptr, nullptr);
}

// round 7
// speedup vs baseline: 1.7881x; 1.1103x over previous
#include <cuda_runtime.h>
#include <cuda_fp16.h>
#include <cstdint>

// Problem constants
#define BB 8
#define TT 256
#define MM 64
#define DD 512
#define HH 8
#define DKK 64
#define NROWS (BB*TT*MM)        // 131072
#define NBTH  (BB*TT*HH)        // 16384

// Scratch (device globals: allocation-free)
__device__ __half g_xh[(size_t)NROWS*DD];      // X in fp16
__device__ __half g_wqkv[3*DD*DD];             // packed Wq|Wk|Wv fp16 (rows = features)
__device__ __half g_wo[DD*DD];                 // Wo fp16
__device__ __half g_a[(size_t)NROWS*DD];       // (btm, d) fp16 attention output

__device__ __forceinline__ uint32_t smem_u32(const void* p) {
    uint32_t a;
    asm("{ .reg .u64 t; cvta.to.shared.u64 t, %1; cvt.u32.u64 %0, t; }" : "=r"(a) : "l"(p));
    return a;
}
__device__ __forceinline__ void cp16(uint32_t saddr, const void* gaddr) {
    asm volatile("cp.async.cg.shared.global [%0], [%1], 16;" :: "r"(saddr), "l"(gaddr) : "memory");
}
__device__ __forceinline__ void cp_commit() {
    asm volatile("cp.async.commit_group;" ::: "memory");
}

__device__ __forceinline__ void mma_f16(float* c,
    uint32_t a0, uint32_t a1, uint32_t a2, uint32_t a3, uint32_t b0, uint32_t b1)
{
    asm volatile(
        "mma.sync.aligned.m16n8k16.row.col.f32.f16.f16.f32 "
        "{%0,%1,%2,%3}, {%4,%5,%6,%7}, {%8,%9}, {%0,%1,%2,%3};"
        : "+f"(c[0]), "+f"(c[1]), "+f"(c[2]), "+f"(c[3])
        : "r"(a0), "r"(a1), "r"(a2), "r"(a3), "r"(b0), "r"(b1));
}

// ---------------------------------------------------------------------------
// conv kernels: fp32 -> fp16
// ---------------------------------------------------------------------------
__global__ void conv_h(const float4* __restrict__ in, uint2* __restrict__ out, int n4)
{
    int i = blockIdx.x * blockDim.x + threadIdx.x;
    if (i >= n4) return;
    float4 v = in[i];
    __half2 h0 = __floats2half2_rn(v.x, v.y);
    __half2 h1 = __floats2half2_rn(v.z, v.w);
    uint2 r;
    r.x = *(uint32_t*)&h0;
    r.y = *(uint32_t*)&h1;
    out[i] = r;
}

__global__ void conv_w(const float4* __restrict__ wq, const float4* __restrict__ wk,
                       const float4* __restrict__ wv, const float4* __restrict__ wo,
                       uint2* __restrict__ oqkv, uint2* __restrict__ oo)
{
    int i = blockIdx.x * blockDim.x + threadIdx.x;   // 0 .. 4*65536-1
    int t = i >> 16, j = i & 65535;
    const float4* src = (t == 0) ? wq : (t == 1) ? wk : (t == 2) ? wv : wo;
    uint2* dst = (t == 3) ? oo : (oqkv + (size_t)t * (DD*DD/4));
    float4 v = src[j];
    __half2 h0 = __floats2half2_rn(v.x, v.y);
    __half2 h1 = __floats2half2_rn(v.z, v.w);
    uint2 r;
    r.x = *(uint32_t*)&h0;
    r.y = *(uint32_t*)&h1;
    dst[j] = r;
}

// ---------------------------------------------------------------------------
// Fused QKV + attention kernel. One CTA per (bt, h), 128 threads (4 warps).
//
// Phase 1 (GEMM): Y[64 x 192] = X[bt rows, 512] @ [Wq_h | Wk_h | Wv_h]^T
//   2-stage cp.async pipeline, BK=64, XOR-swizzled 128B smem rows.
//   Warp tile 64x48 (warp w covers cols [48w, 48w+48)).
//   Epilogue adds bias and writes fp16 directly to smem tiles:
//     cols 0-63   -> qs[m][dk]   (pad 72)
//     cols 64-127 -> ks[m'][dk]  (pad 72)
//     cols 128-191-> vt[dk][m']  (transposed, pad 72)
// Phase 2 (attention, R5-proven body): scores=q@k^T/8 -> softmax -> p@v
//   -> coalesced store to g_a[(bt*64+m)*512 + h*64 + dk].
//
// smem: stages 2 x 32768 B = 65536; qs/ks/vt/ss 4 x 9216 B = 36864. Total 102400.
// ---------------------------------------------------------------------------
#define FSTG 32768
#define FUSED_SMEM 102400

__global__ __launch_bounds__(128, 2)
void qkv_attn_kernel(const float* __restrict__ bq, const float* __restrict__ bk,
                     const float* __restrict__ bv)
{
    extern __shared__ char sm[];
    __half* smh = (__half*)sm;
    const int tid = threadIdx.x, wid = tid >> 5, lane = tid & 31;
    const int g = lane >> 2, tg = lane & 3;
    const int bth = blockIdx.x;
    const int bt = bth >> 3, h = bth & 7;     // h fastest -> adjacent CTAs share X in L2
    const int wn = wid * 48;

    const uint32_t sb = smem_u32(sm);
    const __half* Xp = g_xh + (size_t)bt * 64 * 512;
    const __half* Wb = g_wqkv + (size_t)h * 64 * 512;

    __half* qs  = smh + 32768;      // byte 65536
    __half* ks_ = qs + 4608;
    __half* vt  = ks_ + 4608;
    __half* ss  = vt + 4608;

    float acc[4][6][4];
    #pragma unroll
    for (int a = 0; a < 4; a++)
        #pragma unroll
        for (int b = 0; b < 6; b++)
            #pragma unroll
            for (int c = 0; c < 4; c++) acc[a][b][c] = 0.f;

    auto fill = [&](int s, int kt) {
        uint32_t As = sb + s * FSTG;
        uint32_t Bs = As + 8192;
        int koff = kt * 64;
        #pragma unroll
        for (int it = 0; it < 4; it++) {              // A: 64 rows x 128B
            int i = tid + it * 128;
            int r = i >> 3, c8 = i & 7;
            cp16(As + r * 128 + ((c8 ^ (r & 7)) << 4), Xp + (size_t)r * 512 + koff + c8 * 8);
        }
        #pragma unroll
        for (int it = 0; it < 12; it++) {             // B: 192 rows (3x64) x 128B
            int i = tid + it * 128;
            int r = i >> 3, c8 = i & 7;
            const __half* src = Wb + (size_t)(r >> 6) * (DD*DD) + (size_t)(r & 63) * 512 + koff + c8 * 8;
            cp16(Bs + r * 128 + ((c8 ^ (r & 7)) << 4), src);
        }
        cp_commit();
    };

    fill(0, 0);
    for (int kt = 0; kt < 8; kt++) {
        if (kt + 1 < 8) {
            fill((kt + 1) & 1, kt + 1);
            asm volatile("cp.async.wait_group 1;" ::: "memory");
        } else {
            asm volatile("cp.async.wait_group 0;" ::: "memory");
        }
        __syncthreads();

        char* As = sm + (kt & 1) * FSTG;
        char* Bs = As + 8192;

        #pragma unroll
        for (int ks = 0; ks < 4; ks++) {
            int c0 = ks * 2;
            int sel0 = (c0 ^ g) << 4, sel1 = ((c0 + 1) ^ g) << 4;
            uint32_t af[4][4], bf[6][2];
            #pragma unroll
            for (int im = 0; im < 4; im++) {
                int r = im * 16 + g;
                char* p0 = As + r * 128 + 4 * tg;
                char* p1 = As + (r + 8) * 128 + 4 * tg;
                af[im][0] = *(uint32_t*)(p0 + sel0);
                af[im][1] = *(uint32_t*)(p1 + sel0);
                af[im][2] = *(uint32_t*)(p0 + sel1);
                af[im][3] = *(uint32_t*)(p1 + sel1);
            }
            #pragma unroll
            for (int in = 0; in < 6; in++) {
                int n = wn + in * 8 + g;
                char* p = Bs + n * 128 + 4 * tg;
                bf[in][0] = *(uint32_t*)(p + sel0);
                bf[in][1] = *(uint32_t*)(p + sel1);
            }
            #pragma unroll
            for (int im = 0; im < 4; im++)
                #pragma unroll
                for (int in = 0; in < 6; in++)
                    mma_f16(acc[im][in], af[im][0], af[im][1], af[im][2], af[im][3],
                            bf[in][0], bf[in][1]);
        }
        __syncthreads();
    }

    // epilogue: bias + fp16, route to qs / ks / vt(transposed)
    #pragma unroll
    for (int in = 0; in < 6; in++) {
        int col = wn + in * 8 + 2 * tg;       // even; col,col+1 same region
        int t = col >> 6, lc = col & 63;
        const float* bias = (t == 0) ? bq : (t == 1) ? bk : bv;
        float b0 = bias[h * 64 + lc], b1 = bias[h * 64 + lc + 1];
        #pragma unroll
        for (int im = 0; im < 4; im++) {
            int r0 = im * 16 + g, r1 = r0 + 8;
            __half h00 = __float2half_rn(acc[im][in][0] + b0);
            __half h01 = __float2half_rn(acc[im][in][1] + b1);
            __half h10 = __float2half_rn(acc[im][in][2] + b0);
            __half h11 = __float2half_rn(acc[im][in][3] + b1);
            if (t == 0) {
                __half2 v0; v0.x = h00; v0.y = h01;
                __half2 v1; v1.x = h10; v1.y = h11;
                *(__half2*)(qs + r0 * 72 + lc) = v0;
                *(__half2*)(qs + r1 * 72 + lc) = v1;
            } else if (t == 1) {
                __half2 v0; v0.x = h00; v0.y = h01;
                __half2 v1; v1.x = h10; v1.y = h11;
                *(__half2*)(ks_ + r0 * 72 + lc) = v0;
                *(__half2*)(ks_ + r1 * 72 + lc) = v1;
            } else {
                vt[lc * 72 + r0] = h00; vt[(lc + 1) * 72 + r0] = h01;
                vt[lc * 72 + r1] = h10; vt[(lc + 1) * 72 + r1] = h11;
            }
        }
    }
    __syncthreads();   // q/k/vt tiles complete across all warps

    // ------------- attention (R5 body) -------------
    const int mr = wid * 16;
    float c[8][4];
    #pragma unroll
    for (int in = 0; in < 8; in++)
        #pragma unroll
        for (int j = 0; j < 4; j++) c[in][j] = 0.f;

    // scores = q @ k^T
    #pragma unroll
    for (int ks4 = 0; ks4 < 4; ks4++) {
        int koff = ks4 * 16;
        uint32_t a0 = *(uint32_t*)(qs + (mr + g    ) * 72 + koff + 2 * tg);
        uint32_t a1 = *(uint32_t*)(qs + (mr + g + 8) * 72 + koff + 2 * tg);
        uint32_t a2 = *(uint32_t*)(qs + (mr + g    ) * 72 + koff + 2 * tg + 8);
        uint32_t a3 = *(uint32_t*)(qs + (mr + g + 8) * 72 + koff + 2 * tg + 8);
        #pragma unroll
        for (int in = 0; in < 8; in++) {
            int nr = in * 8 + g;
            uint32_t b0 = *(uint32_t*)(ks_ + nr * 72 + koff + 2 * tg);
            uint32_t b1 = *(uint32_t*)(ks_ + nr * 72 + koff + 2 * tg + 8);
            mma_f16(c[in], a0, a1, a2, a3, b0, b1);
        }
    }

    // softmax (scale 1/8)
    const float scale = 0.125f;
    float mx0 = -1e30f, mx1 = -1e30f;
    #pragma unroll
    for (int in = 0; in < 8; in++) {
        c[in][0] *= scale; c[in][1] *= scale;
        c[in][2] *= scale; c[in][3] *= scale;
        mx0 = fmaxf(mx0, fmaxf(c[in][0], c[in][1]));
        mx1 = fmaxf(mx1, fmaxf(c[in][2], c[in][3]));
    }
    mx0 = fmaxf(mx0, __shfl_xor_sync(0xffffffffu, mx0, 1));
    mx0 = fmaxf(mx0, __shfl_xor_sync(0xffffffffu, mx0, 2));
    mx1 = fmaxf(mx1, __shfl_xor_sync(0xffffffffu, mx1, 1));
    mx1 = fmaxf(mx1, __shfl_xor_sync(0xffffffffu, mx1, 2));

    float s0 = 0.f, s1 = 0.f;
    #pragma unroll
    for (int in = 0; in < 8; in++) {
        c[in][0] = __expf(c[in][0] - mx0); s0 += c[in][0];
        c[in][1] = __expf(c[in][1] - mx0); s0 += c[in][1];
        c[in][2] = __expf(c[in][2] - mx1); s1 += c[in][2];
        c[in][3] = __expf(c[in][3] - mx1); s1 += c[in][3];
    }
    s0 += __shfl_xor_sync(0xffffffffu, s0, 1);
    s0 += __shfl_xor_sync(0xffffffffu, s0, 2);
    s1 += __shfl_xor_sync(0xffffffffu, s1, 1);
    s1 += __shfl_xor_sync(0xffffffffu, s1, 2);
    float inv0 = 1.f / s0, inv1 = 1.f / s1;

    // write P (own warp rows)
    #pragma unroll
    for (int in = 0; in < 8; in++) {
        int col = in * 8 + 2 * tg;
        *(__half2*)(ss + (mr + g    ) * 72 + col) = __floats2half2_rn(c[in][0] * inv0, c[in][1] * inv0);
        *(__half2*)(ss + (mr + g + 8) * 72 + col) = __floats2half2_rn(c[in][2] * inv1, c[in][3] * inv1);
    }
    __syncwarp();

    #pragma unroll
    for (int in = 0; in < 8; in++)
        #pragma unroll
        for (int j = 0; j < 4; j++) c[in][j] = 0.f;

    // out = P @ V   (A = ss[m][m'] own rows, B[k=m'][n=dk] = vt[dk][m'])
    #pragma unroll
    for (int ks4 = 0; ks4 < 4; ks4++) {
        int koff = ks4 * 16;
        uint32_t a0 = *(uint32_t*)(ss + (mr + g    ) * 72 + koff + 2 * tg);
        uint32_t a1 = *(uint32_t*)(ss + (mr + g + 8) * 72 + koff + 2 * tg);
        uint32_t a2 = *(uint32_t*)(ss + (mr + g    ) * 72 + koff + 2 * tg + 8);
        uint32_t a3 = *(uint32_t*)(ss + (mr + g + 8) * 72 + koff + 2 * tg + 8);
        #pragma unroll
        for (int in = 0; in < 8; in++) {
            int nr = in * 8 + g;
            uint32_t b0 = *(uint32_t*)(vt + nr * 72 + koff + 2 * tg);
            uint32_t b1 = *(uint32_t*)(vt + nr * 72 + koff + 2 * tg + 8);
            mma_f16(c[in], a0, a1, a2, a3, b0, b1);
        }
    }

    // stage output tile into ss (own warp rows)
    #pragma unroll
    for (int in = 0; in < 8; in++) {
        int col = in * 8 + 2 * tg;
        *(__half2*)(ss + (mr + g    ) * 72 + col) = __floats2half2_rn(c[in][0], c[in][1]);
        *(__half2*)(ss + (mr + g + 8) * 72 + col) = __floats2half2_rn(c[in][2], c[in][3]);
    }
    __syncthreads();

    // coalesced store: 2 threads per row, 64B each -> full 128B segments
    {
        __half* dst = g_a + ((size_t)bt * 64) * 512 + h * 64;
        int row = tid >> 1, part = tid & 1;
        const uint4* sp = (const uint4*)(ss + row * 72 + part * 32);
        uint4* dp = (uint4*)(dst + (size_t)row * 512 + part * 32);
        dp[0] = sp[0]; dp[1] = sp[1]; dp[2] = sp[2]; dp[3] = sp[3];
    }
}

// ---------------------------------------------------------------------------
// Out-projection GEMM (R6-proven, MODE 1 only): D[128x128] of out = g_a @ Wo^T + bo
// 3-stage cp.async, BK=64, 4 warps of 64x64.
// ---------------------------------------------------------------------------
#define STG 32768
#define GEMM_SMEM (3*STG)

__device__ __forceinline__ void fill_stage(uint32_t smem_base, int s,
                                           const __half* __restrict__ Ap,
                                           const __half* __restrict__ Bp,
                                           int kt, int tid)
{
    uint32_t As = smem_base + s * STG;
    uint32_t Bs = As + 16384;
    int koff = kt * 64;
    #pragma unroll
    for (int it = 0; it < 8; it++) {
        int i = tid + it * 128;
        int r = i >> 3, c8 = i & 7;
        cp16(As + r * 128 + ((c8 ^ (r & 7)) << 4), Ap + (size_t)r * 512 + koff + c8 * 8);
    }
    #pragma unroll
    for (int it = 0; it < 8; it++) {
        int i = tid + it * 128;
        int r = i >> 3, c8 = i & 7;
        cp16(Bs + r * 128 + ((c8 ^ (r & 7)) << 4), Bp + (size_t)r * 512 + koff + c8 * 8);
    }
    cp_commit();
}

__global__ __launch_bounds__(128, 2)
void gemm_out(const __half* __restrict__ A, const __half* __restrict__ Bw,
              const float* __restrict__ bias, float* __restrict__ out)
{
    extern __shared__ char sm[];
    const int tid = threadIdx.x, wid = tid >> 5, lane = tid & 31;
    const int g = lane >> 2, tg = lane & 3;
    const int n0 = blockIdx.x * 128, m0 = blockIdx.y * 128;
    const int wm = (wid & 1) * 64, wn = (wid >> 1) * 64;

    uint32_t sbase = smem_u32(sm);
    const __half* Ap = A + (size_t)m0 * 512;
    const __half* Bp = Bw + (size_t)n0 * 512;

    float acc[4][8][4];
    #pragma unroll
    for (int a = 0; a < 4; a++)
        #pragma unroll
        for (int b = 0; b < 8; b++)
            #pragma unroll
            for (int c = 0; c < 4; c++) acc[a][b][c] = 0.f;

    fill_stage(sbase, 0, Ap, Bp, 0, tid);
    fill_stage(sbase, 1, Ap, Bp, 1, tid);

    for (int kt = 0; kt < 8; kt++) {
        if (kt < 7) asm volatile("cp.async.wait_group 1;" ::: "memory");
        else        asm volatile("cp.async.wait_group 0;" ::: "memory");
        __syncthreads();
        if (kt + 2 < 8) fill_stage(sbase, (kt + 2) % 3, Ap, Bp, kt + 2, tid);

        char* As = sm + (kt % 3) * STG;
        char* Bs = As + 16384;

        #pragma unroll
        for (int ks = 0; ks < 4; ks++) {
            int c0 = ks * 2;
            int sel0 = (c0 ^ g) << 4, sel1 = ((c0 + 1) ^ g) << 4;
            uint32_t af[4][4], bf[8][2];
            #pragma unroll
            for (int im = 0; im < 4; im++) {
                int r = wm + im * 16 + g;
                char* p0 = As + r * 128 + 4 * tg;
                char* p1 = As + (r + 8) * 128 + 4 * tg;
                af[im][0] = *(uint32_t*)(p0 + sel0);
                af[im][1] = *(uint32_t*)(p1 + sel0);
                af[im][2] = *(uint32_t*)(p0 + sel1);
                af[im][3] = *(uint32_t*)(p1 + sel1);
            }
            #pragma unroll
            for (int in = 0; in < 8; in++) {
                int n = wn + in * 8 + g;
                char* p = Bs + n * 128 + 4 * tg;
                bf[in][0] = *(uint32_t*)(p + sel0);
                bf[in][1] = *(uint32_t*)(p + sel1);
            }
            #pragma unroll
            for (int im = 0; im < 4; im++)
                #pragma unroll
                for (int in = 0; in < 8; in++)
                    mma_f16(acc[im][in], af[im][0], af[im][1], af[im][2], af[im][3],
                            bf[in][0], bf[in][1]);
        }
        __syncthreads();
    }

    #pragma unroll
    for (int im = 0; im < 4; im++) {
        #pragma unroll
        for (int in = 0; in < 8; in++) {
            int col = n0 + wn + in * 8 + 2 * tg;
            float bb0 = bias[col], bb1 = bias[col + 1];
            int r0 = m0 + wm + im * 16 + g;
            float2 v0 = {acc[im][in][0] + bb0, acc[im][in][1] + bb1};
            float2 v1 = {acc[im][in][2] + bb0, acc[im][in][3] + bb1};
            *(float2*)(out + (size_t)r0 * 512 + col) = v0;
            *(float2*)(out + (size_t)(r0 + 8) * 512 + col) = v1;
        }
    }
}

// ---------------------------------------------------------------------------
extern "C" void kernel_launch(void* const* d_in, const int* in_sizes, int n_in,
                              void* d_out, int out_size)
{
    const float* x  = (const float*)d_in[0];
    const float* Wq = (const float*)d_in[1];
    const float* bq = (const float*)d_in[2];
    const float* Wk = (const float*)d_in[3];
    const float* bk = (const float*)d_in[4];
    const float* Wv = (const float*)d_in[5];
    const float* bv = (const float*)d_in[6];
    const float* Wo = (const float*)d_in[7];
    const float* bo = (const float*)d_in[8];
    float* out = (float*)d_out;

    void *pxh, *pwqkv, *pwo, *pa;
    cudaGetSymbolAddress(&pxh,   g_xh);
    cudaGetSymbolAddress(&pwqkv, g_wqkv);
    cudaGetSymbolAddress(&pwo,   g_wo);
    cudaGetSymbolAddress(&pa,    g_a);

    // 1) fp32 -> fp16 conversions
    conv_h<<<(NROWS*DD/4 + 255)/256, 256>>>((const float4*)x, (uint2*)pxh, NROWS*DD/4);
    conv_w<<<(4*DD*DD/4 + 255)/256, 256>>>((const float4*)Wq, (const float4*)Wk,
                                           (const float4*)Wv, (const float4*)Wo,
                                           (uint2*)pwqkv, (uint2*)pwo);

    cudaFuncSetAttribute(qkv_attn_kernel, cudaFuncAttributeMaxDynamicSharedMemorySize, FUSED_SMEM);
    cudaFuncSetAttribute(gemm_out, cudaFuncAttributeMaxDynamicSharedMemorySize, GEMM_SMEM);

    // 2) fused QKV projection + attention: one CTA per (bt, h)
    qkv_attn_kernel<<<NBTH, 128, FUSED_SMEM>>>(bq, bk, bv);

    // 3) output projection: out = g_a @ Wo^T + bo
    dim3 go(4, NROWS / 128);
    gemm_out<<<go, 128, GEMM_SMEM>>>((const __half*)pa, (const __half*)pwo, bo, out);
}